// round 1
// baseline (speedup 1.0000x reference)
#include <cuda_runtime.h>
#include <math.h>

#define BB   128
#define TT   256
#define HH   1024
#define KG   256      /* HH/4 feature-groups */
#define NBLK 128
#define NJ   8        /* output cols per CTA */
#define NTH  256

/* Scratch (static device globals; no runtime allocation). */
__device__ float4 g_pre0[(size_t)TT * KG * BB];   /* [t][j4][b], 128 MB */
__device__ float4 g_h0buf[2][KG * BB];            /* layer-0 hidden, double buffered, [k4][b] */
__device__ float4 g_h1buf[2][KG * BB];            /* layer-1 hidden */
__device__ unsigned int g_cnt;                    /* grid barrier counter (monotonic per launch) */

/* ------------------------------------------------------------------ */
/* Kernel 1: pre0[t][j][b] = sum_k x[b][t][k]*Wi0[k][j] + bi0[j]       */
/* grid = (16 colgroups, 256 t), 256 threads, tile 128(b) x 64(j)      */
/* ------------------------------------------------------------------ */
__global__ __launch_bounds__(256) void pre_gemm(const float* __restrict__ x,
                                                const float* __restrict__ Wi,
                                                const float* __restrict__ bi)
{
    if (blockIdx.x == 0 && blockIdx.y == 0 && threadIdx.x == 0) g_cnt = 0u;

    __shared__ float  sA[32][129];     /* x tile transposed: [k][b], padded */
    __shared__ float4 sB[32 * 16];     /* Wi0 tile: [k][j/4] */

    const int t     = blockIdx.y;
    const int jbase = blockIdx.x * 64;
    const int tid   = threadIdx.x;
    const int rid   = tid & 31;        /* lane -> row offset */
    const int cid   = tid >> 5;        /* warp -> 8-col group (warp-uniform) */

    float acc[4][8];
#pragma unroll
    for (int i = 0; i < 4; ++i)
#pragma unroll
        for (int j = 0; j < 8; ++j) acc[i][j] = 0.0f;

    const int brow = tid >> 1;         /* A-loader row */
    const int half = tid & 1;

    for (int k0 = 0; k0 < HH; k0 += 32) {
        __syncthreads();
        /* stage A (transpose x[b][t][k0..k0+31] -> sA[k][b]) */
        const float* xs = x + ((size_t)brow * TT + t) * HH + k0 + half * 16;
#pragma unroll
        for (int q = 0; q < 4; ++q) {
            float4 v = *(const float4*)(xs + 4 * q);
            int kk = half * 16 + 4 * q;
            sA[kk + 0][brow] = v.x; sA[kk + 1][brow] = v.y;
            sA[kk + 2][brow] = v.z; sA[kk + 3][brow] = v.w;
        }
        /* stage B (Wi0 rows, coalesced) */
#pragma unroll
        for (int q = 0; q < 2; ++q) {
            int idx = tid + 256 * q;
            int kk = idx >> 4, jf = idx & 15;
            sB[idx] = *(const float4*)(Wi + (size_t)(k0 + kk) * HH + jbase + 4 * jf);
        }
        __syncthreads();

#pragma unroll
        for (int kk = 0; kk < 32; ++kk) {
            float a0 = sA[kk][rid], a1 = sA[kk][rid + 32];
            float a2 = sA[kk][rid + 64], a3 = sA[kk][rid + 96];
            float4 b0 = sB[kk * 16 + cid * 2];
            float4 b1 = sB[kk * 16 + cid * 2 + 1];
            float bv[8] = {b0.x, b0.y, b0.z, b0.w, b1.x, b1.y, b1.z, b1.w};
#pragma unroll
            for (int j = 0; j < 8; ++j) {
                acc[0][j] = fmaf(a0, bv[j], acc[0][j]);
                acc[1][j] = fmaf(a1, bv[j], acc[1][j]);
                acc[2][j] = fmaf(a2, bv[j], acc[2][j]);
                acc[3][j] = fmaf(a3, bv[j], acc[3][j]);
            }
        }
    }

    float biv[8];
#pragma unroll
    for (int j = 0; j < 8; ++j) biv[j] = __ldg(&bi[jbase + cid * 8 + j]);

    const int jg = (jbase + cid * 8) >> 2;
#pragma unroll
    for (int i = 0; i < 4; ++i) {
        int row = rid + 32 * i;
#pragma unroll
        for (int g = 0; g < 2; ++g) {
            float4 v;
            v.x = acc[i][4 * g + 0] + biv[4 * g + 0];
            v.y = acc[i][4 * g + 1] + biv[4 * g + 1];
            v.z = acc[i][4 * g + 2] + biv[4 * g + 2];
            v.w = acc[i][4 * g + 3] + biv[4 * g + 3];
            g_pre0[((size_t)t * KG + jg + g) * BB + row] = v;
        }
    }
}

/* ------------------------------------------------------------------ */
/* Grid barrier: monotonic counter, threshold known per phase.         */
/* ------------------------------------------------------------------ */
__device__ __forceinline__ void grid_sync(unsigned int target)
{
    __syncthreads();
    if (threadIdx.x == 0) {
        __threadfence();
        atomicAdd(&g_cnt, 1u);
        while (*(volatile unsigned int*)&g_cnt < target) { }
        __threadfence();
    }
    __syncthreads();
}

/* ------------------------------------------------------------------ */
/* Kernel 2: persistent weight-stationary RNN.                         */
/* 128 CTAs (1/SM), 256 threads. CTA owns 8 output columns of all of   */
/* Wh0, Wi1, Wh1 (SMEM-resident). One grid barrier per timestep.       */
/* Phase t: hn1[t] = tanh(hn0[t]@Wi1 + h1[t-1]@Wh1 + bi1 + bh1)        */
/*          hn0[t+1] = tanh(pre0[t+1] + hn0[t]@Wh0 + bh0)              */
/* ------------------------------------------------------------------ */
__global__ __launch_bounds__(NTH, 1) void rnn_persist(const float* __restrict__ h0,
                                                      const float* __restrict__ Wi,
                                                      const float* __restrict__ bi,
                                                      const float* __restrict__ Wh,
                                                      const float* __restrict__ bh,
                                                      float* __restrict__ out)
{
    extern __shared__ float4 smem4[];
    float4* sWh0 = smem4;          /* [8][256] col-slices, float4 over k */
    float4* sWi1 = smem4 + 2048;
    float4* sWh1 = smem4 + 4096;
    float*  sred = (float*)(smem4 + 6144);   /* [16][128] partial-sum exchange */

    const int cta = blockIdx.x;
    const int tid = threadIdx.x;
    const int wg  = tid >> 7;      /* K-half: warps 0-3 low K, 4-7 high K */
    const int r   = tid & 127;     /* batch row */
    const int j0  = cta * NJ;
    const int jg  = j0 >> 2;

    const float* Wi1g = Wi + (size_t)HH * HH;
    const float* Wh1g = Wh + (size_t)HH * HH;

    /* One-time: gather weight column slices into SMEM (float4 over k). */
    for (int idx = tid; idx < 2048; idx += NTH) {
        int jl = idx >> 8, k4 = idx & 255;
        int j = j0 + jl;
        int kb = k4 * 4;
        sWh0[idx] = make_float4(Wh[(size_t)(kb + 0) * HH + j], Wh[(size_t)(kb + 1) * HH + j],
                                Wh[(size_t)(kb + 2) * HH + j], Wh[(size_t)(kb + 3) * HH + j]);
        sWi1[idx] = make_float4(Wi1g[(size_t)(kb + 0) * HH + j], Wi1g[(size_t)(kb + 1) * HH + j],
                                Wi1g[(size_t)(kb + 2) * HH + j], Wi1g[(size_t)(kb + 3) * HH + j]);
        sWh1[idx] = make_float4(Wh1g[(size_t)(kb + 0) * HH + j], Wh1g[(size_t)(kb + 1) * HH + j],
                                Wh1g[(size_t)(kb + 2) * HH + j], Wh1g[(size_t)(kb + 3) * HH + j]);
    }

    float bsum1[NJ], b0c[NJ];
#pragma unroll
    for (int jj = 0; jj < NJ; ++jj) {
        bsum1[jj] = __ldg(&bi[HH + j0 + jj]) + __ldg(&bh[HH + j0 + jj]);
        b0c[jj]   = __ldg(&bh[j0 + jj]);
    }
    __syncthreads();

    /* Init: hn0[0] = tanh(pre0[0] + h0_l0 @ Wh0 + bh0); rows share the dot term. */
    if (wg == 0) {
        float dot0[NJ];
#pragma unroll
        for (int jj = 0; jj < NJ; ++jj) dot0[jj] = 0.0f;
        for (int k4 = 0; k4 < KG; ++k4) {
            float4 a = *(const float4*)(h0 + 4 * k4);
#pragma unroll
            for (int jj = 0; jj < NJ; ++jj) {
                float4 w = sWh0[jj * 256 + k4];
                dot0[jj] = fmaf(a.x, w.x, fmaf(a.y, w.y, fmaf(a.z, w.z, fmaf(a.w, w.w, dot0[jj]))));
            }
        }
#pragma unroll
        for (int g = 0; g < 2; ++g) {
            float4 pre = g_pre0[(size_t)(jg + g) * BB + r];   /* t = 0 */
            float4 v;
            v.x = tanhf(pre.x + dot0[4 * g + 0] + b0c[4 * g + 0]);
            v.y = tanhf(pre.y + dot0[4 * g + 1] + b0c[4 * g + 1]);
            v.z = tanhf(pre.z + dot0[4 * g + 2] + b0c[4 * g + 2]);
            v.w = tanhf(pre.w + dot0[4 * g + 3] + b0c[4 * g + 3]);
            g_h0buf[0][(jg + g) * BB + r] = v;
        }
    }
    /* Init h1[-1] = broadcast h0 layer 1 (CTA covers k4 in [2*cta, 2*cta+2)). */
    {
        int k4loc = 2 * cta + wg;
        float4 hv = *(const float4*)(h0 + HH + 4 * k4loc);
        g_h1buf[1][k4loc * BB + r] = hv;
    }

    unsigned int ph = 1;
    grid_sync(ph * NBLK); ++ph;

    const int kb = wg << 7;   /* this warp-group's K-half start (k4 units) */

    for (int t = 0; t < TT; ++t) {
        const float4* A0 = g_h0buf[t & 1];
        const float4* A1 = g_h1buf[(t + 1) & 1];

        float acc1[NJ], acc0[NJ];
#pragma unroll
        for (int jj = 0; jj < NJ; ++jj) { acc1[jj] = 0.0f; acc0[jj] = 0.0f; }

        /* Loop 1: over hn0[t] — feeds both hn1 (Wi1) and hn0[t+1] (Wh0). */
        for (int k4 = 0; k4 < 128; ++k4) {
            int off = kb + k4;
            float4 a = __ldcg(&A0[off * BB + r]);
#pragma unroll
            for (int jj = 0; jj < NJ; ++jj) {
                float4 w1 = sWi1[jj * 256 + off];
                acc1[jj] = fmaf(a.x, w1.x, fmaf(a.y, w1.y, fmaf(a.z, w1.z, fmaf(a.w, w1.w, acc1[jj]))));
                float4 w0 = sWh0[jj * 256 + off];
                acc0[jj] = fmaf(a.x, w0.x, fmaf(a.y, w0.y, fmaf(a.z, w0.z, fmaf(a.w, w0.w, acc0[jj]))));
            }
        }
        /* Loop 2: over h1[t-1] — feeds hn1 (Wh1). */
        for (int k4 = 0; k4 < 128; ++k4) {
            int off = kb + k4;
            float4 a = __ldcg(&A1[off * BB + r]);
#pragma unroll
            for (int jj = 0; jj < NJ; ++jj) {
                float4 w = sWh1[jj * 256 + off];
                acc1[jj] = fmaf(a.x, w.x, fmaf(a.y, w.y, fmaf(a.z, w.z, fmaf(a.w, w.w, acc1[jj]))));
            }
        }

        /* Cross-K-half reduction. */
        if (wg == 1) {
#pragma unroll
            for (int jj = 0; jj < NJ; ++jj) {
                sred[jj * 128 + r]       = acc1[jj];
                sred[(8 + jj) * 128 + r] = acc0[jj];
            }
        }
        __syncthreads();

        if (wg == 0) {
#pragma unroll
            for (int jj = 0; jj < NJ; ++jj) {
                acc1[jj] += sred[jj * 128 + r];
                acc0[jj] += sred[(8 + jj) * 128 + r];
            }
            float y[NJ];
#pragma unroll
            for (int jj = 0; jj < NJ; ++jj) y[jj] = tanhf(acc1[jj] + bsum1[jj]);
            float4 v0 = make_float4(y[0], y[1], y[2], y[3]);
            float4 v1 = make_float4(y[4], y[5], y[6], y[7]);

            /* output[b][t][j] */
            float* yp = out + ((size_t)r * TT + t) * HH + j0;
            *(float4*)(yp)     = v0;
            *(float4*)(yp + 4) = v1;
            /* h1[t] */
            g_h1buf[t & 1][jg * BB + r]       = v0;
            g_h1buf[t & 1][(jg + 1) * BB + r] = v1;

            if (t < TT - 1) {
                float4 pa = __ldg(&g_pre0[((size_t)(t + 1) * KG + jg) * BB + r]);
                float4 pb = __ldg(&g_pre0[((size_t)(t + 1) * KG + jg + 1) * BB + r]);
                float4 ha, hb;
                ha.x = tanhf(acc0[0] + pa.x + b0c[0]);
                ha.y = tanhf(acc0[1] + pa.y + b0c[1]);
                ha.z = tanhf(acc0[2] + pa.z + b0c[2]);
                ha.w = tanhf(acc0[3] + pa.w + b0c[3]);
                hb.x = tanhf(acc0[4] + pb.x + b0c[4]);
                hb.y = tanhf(acc0[5] + pb.y + b0c[5]);
                hb.z = tanhf(acc0[6] + pb.z + b0c[6]);
                hb.w = tanhf(acc0[7] + pb.w + b0c[7]);
                g_h0buf[(t + 1) & 1][jg * BB + r]       = ha;
                g_h0buf[(t + 1) & 1][(jg + 1) * BB + r] = hb;
            } else {
                /* h_n: [B][L][H]; layer1 = hn1[T-1], layer0 = hn0[T-1] */
                float* hn = out + (size_t)BB * TT * HH;
                float* p1 = hn + (size_t)(r * 2 + 1) * HH + j0;
                *(float4*)(p1)     = v0;
                *(float4*)(p1 + 4) = v1;
                float4 l0a = __ldcg(&g_h0buf[t & 1][jg * BB + r]);
                float4 l0b = __ldcg(&g_h0buf[t & 1][(jg + 1) * BB + r]);
                float* p0 = hn + (size_t)(r * 2) * HH + j0;
                *(float4*)(p0)     = l0a;
                *(float4*)(p0 + 4) = l0b;
            }
        }

        if (t < TT - 1) { grid_sync(ph * NBLK); ++ph; }
    }
}

/* ------------------------------------------------------------------ */
extern "C" void kernel_launch(void* const* d_in, const int* in_sizes, int n_in,
                              void* d_out, int out_size)
{
    const float* x  = (const float*)d_in[0];
    const float* h0 = (const float*)d_in[1];
    const float* Wi = (const float*)d_in[2];
    const float* bi = (const float*)d_in[3];
    const float* Wh = (const float*)d_in[4];
    const float* bh = (const float*)d_in[5];
    float* out = (float*)d_out;

    dim3 g2(16, 256);
    pre_gemm<<<g2, 256>>>(x, Wi, bi);

    size_t smem = 6144 * sizeof(float4) + 16 * 128 * sizeof(float);  /* 106.5 KB */
    cudaFuncSetAttribute(rnn_persist, cudaFuncAttributeMaxDynamicSharedMemorySize, (int)smem);
    rnn_persist<<<NBLK, NTH, smem>>>(h0, Wi, bi, Wh, bh, out);
}

// round 2
// speedup vs baseline: 1.9728x; 1.9728x over previous
#include <cuda_runtime.h>
#include <math.h>

#define BB   128
#define TT   256
#define HH   1024
#define KG   256     /* HH/4 feature-groups */
#define NBLK 128
#define NJ   8       /* output cols per CTA */
#define NTH  512
#define NGR  8       /* K groups per CTA */
#define K4G  32      /* k4 steps per group */

typedef unsigned long long u64;

/* Scratch (static device globals; no runtime allocation). */
__device__ float4 g_pre0[(size_t)TT * KG * BB];   /* [t][j4][b] */
__device__ float4 g_h0buf[2][KG * BB];            /* layer-0 hidden, double buffered, [k4][b] */
__device__ float4 g_h1buf[2][KG * BB];            /* layer-1 hidden */
__device__ unsigned int g_cnt;                    /* grid barrier counter */

/* ---------------- packed fp32x2 helpers (FFMA2 path) ---------------- */
__device__ __forceinline__ u64 fma2(u64 a, u64 b, u64 c) {
    u64 d; asm("fma.rn.f32x2 %0, %1, %2, %3;" : "=l"(d) : "l"(a), "l"(b), "l"(c)); return d;
}
__device__ __forceinline__ u64 pack2(float x, float y) {
    u64 r; asm("mov.b64 %0, {%1, %2};" : "=l"(r) : "f"(x), "f"(y)); return r;
}
__device__ __forceinline__ float2 unpk(u64 v) {
    float2 f; asm("mov.b64 {%0, %1}, %2;" : "=f"(f.x), "=f"(f.y) : "l"(v)); return f;
}
/* 16B L1-bypassing load returning two packed f32x2 operands. */
__device__ __forceinline__ void ldcg2(const float4* p, u64& x, u64& y) {
    asm("ld.global.cg.v2.u64 {%0,%1}, [%2];" : "=l"(x), "=l"(y) : "l"(p));
}

/* ------------------------------------------------------------------ */
/* Kernel 1: pre0[t][j][b] = sum_k x[b][t][k]*Wi0[k][j] + bi0[j]       */
/* grid = (16 colgroups, 256 t), 256 threads, tile 128(b) x 64(j)      */
/* ------------------------------------------------------------------ */
__global__ __launch_bounds__(256) void pre_gemm(const float* __restrict__ x,
                                                const float* __restrict__ Wi,
                                                const float* __restrict__ bi)
{
    if (blockIdx.x == 0 && blockIdx.y == 0 && threadIdx.x == 0) g_cnt = 0u;

    __shared__ float  sA[32][129];     /* x tile transposed: [k][b], padded */
    __shared__ float4 sB[32 * 16];     /* Wi0 tile: [k][j/4] */

    const int t     = blockIdx.y;
    const int jbase = blockIdx.x * 64;
    const int tid   = threadIdx.x;
    const int rid   = tid & 31;
    const int cid   = tid >> 5;

    u64 acc[4][4];                     /* [row-grp][j-pair] packed f32x2 */
#pragma unroll
    for (int i = 0; i < 4; ++i)
#pragma unroll
        for (int j = 0; j < 4; ++j) acc[i][j] = 0ull;

    const int brow = tid >> 1;
    const int half = tid & 1;

    for (int k0 = 0; k0 < HH; k0 += 32) {
        __syncthreads();
        const float* xs = x + ((size_t)brow * TT + t) * HH + k0 + half * 16;
#pragma unroll
        for (int q = 0; q < 4; ++q) {
            float4 v = *(const float4*)(xs + 4 * q);
            int kk = half * 16 + 4 * q;
            sA[kk + 0][brow] = v.x; sA[kk + 1][brow] = v.y;
            sA[kk + 2][brow] = v.z; sA[kk + 3][brow] = v.w;
        }
#pragma unroll
        for (int q = 0; q < 2; ++q) {
            int idx = tid + 256 * q;
            int kk = idx >> 4, jf = idx & 15;
            sB[idx] = *(const float4*)(Wi + (size_t)(k0 + kk) * HH + jbase + 4 * jf);
        }
        __syncthreads();

#pragma unroll
        for (int kk = 0; kk < 32; ++kk) {
            float a0 = sA[kk][rid], a1 = sA[kk][rid + 32];
            float a2 = sA[kk][rid + 64], a3 = sA[kk][rid + 96];
            const ulonglong2* bp = (const ulonglong2*)&sB[kk * 16 + cid * 2];
            ulonglong2 bb0 = bp[0];   /* cols (0,1),(2,3) of this warp's 8 */
            ulonglong2 bb1 = bp[1];   /* cols (4,5),(6,7) */
            u64 ad0 = pack2(a0, a0), ad1 = pack2(a1, a1);
            u64 ad2 = pack2(a2, a2), ad3 = pack2(a3, a3);
            acc[0][0] = fma2(ad0, bb0.x, acc[0][0]); acc[0][1] = fma2(ad0, bb0.y, acc[0][1]);
            acc[0][2] = fma2(ad0, bb1.x, acc[0][2]); acc[0][3] = fma2(ad0, bb1.y, acc[0][3]);
            acc[1][0] = fma2(ad1, bb0.x, acc[1][0]); acc[1][1] = fma2(ad1, bb0.y, acc[1][1]);
            acc[1][2] = fma2(ad1, bb1.x, acc[1][2]); acc[1][3] = fma2(ad1, bb1.y, acc[1][3]);
            acc[2][0] = fma2(ad2, bb0.x, acc[2][0]); acc[2][1] = fma2(ad2, bb0.y, acc[2][1]);
            acc[2][2] = fma2(ad2, bb1.x, acc[2][2]); acc[2][3] = fma2(ad2, bb1.y, acc[2][3]);
            acc[3][0] = fma2(ad3, bb0.x, acc[3][0]); acc[3][1] = fma2(ad3, bb0.y, acc[3][1]);
            acc[3][2] = fma2(ad3, bb1.x, acc[3][2]); acc[3][3] = fma2(ad3, bb1.y, acc[3][3]);
        }
    }

    float biv[8];
#pragma unroll
    for (int j = 0; j < 8; ++j) biv[j] = __ldg(&bi[jbase + cid * 8 + j]);

    const int jg = (jbase + cid * 8) >> 2;
#pragma unroll
    for (int i = 0; i < 4; ++i) {
        int row = rid + 32 * i;
#pragma unroll
        for (int gq = 0; gq < 2; ++gq) {
            float2 u0 = unpk(acc[i][2 * gq]);
            float2 u1 = unpk(acc[i][2 * gq + 1]);
            float4 v;
            v.x = u0.x + biv[4 * gq + 0];
            v.y = u0.y + biv[4 * gq + 1];
            v.z = u1.x + biv[4 * gq + 2];
            v.w = u1.y + biv[4 * gq + 3];
            g_pre0[((size_t)t * KG + jg + gq) * BB + row] = v;
        }
    }
}

/* ------------------------------------------------------------------ */
__device__ __forceinline__ void grid_sync(unsigned int target)
{
    __syncthreads();
    if (threadIdx.x == 0) {
        __threadfence();
        atomicAdd(&g_cnt, 1u);
        while (*(volatile unsigned int*)&g_cnt < target) { }
        __threadfence();
    }
    __syncthreads();
}

#define RIDX(i, g, s) ((((i) * 8 + (g)) * 65) + (s))

/* ------------------------------------------------------------------ */
/* Kernel 2: persistent weight-stationary RNN, FFMA2 inner loops.      */
/* 128 CTAs x 512 thr. thread = (K-group g of 8, row-slot of 64);      */
/* each thread handles rows slot and slot+64 (halves LDS per FLOP).    */
/* ------------------------------------------------------------------ */
__global__ __launch_bounds__(NTH, 1) void rnn_persist(const float* __restrict__ h0,
                                                      const float* __restrict__ Wi,
                                                      const float* __restrict__ bi,
                                                      const float* __restrict__ Wh,
                                                      const float* __restrict__ bh,
                                                      float* __restrict__ out)
{
    extern __shared__ float4 smem4[];
    float4* sWh0 = smem4;              /* [8][256] col-slices */
    float4* sWi1 = smem4 + 2048;
    float4* sWh1 = smem4 + 4096;
    float*  sred = (float*)(smem4 + 6144);          /* [32][8][65] partials */
    float*  sdot = sred + 32 * 8 * 65;              /* [8][8] init dot */

    const int cta  = blockIdx.x;
    const int th   = threadIdx.x;
    const int g    = th >> 6;          /* K group 0..7 */
    const int slot = th & 63;          /* row slot: rows slot, slot+64 */
    const int j0   = cta * NJ;

    /* final-pass mapping (all 512 threads): */
    const int frow = th >> 2;          /* 0..127 */
    const int c0   = (th & 3) * 2;     /* cols c0, c0+1 of this CTA's 8 */
    const int fslot = frow & 63;
    const int frh   = frow >> 6;

    const float* Wi1g = Wi + (size_t)HH * HH;
    const float* Wh1g = Wh + (size_t)HH * HH;

    /* One-time: gather weight column slices into SMEM (float4 over k). */
    for (int idx = th; idx < 2048; idx += NTH) {
        int jl = idx >> 8, k4 = idx & 255;
        int j = j0 + jl;
        int kb = k4 * 4;
        sWh0[idx] = make_float4(Wh[(size_t)(kb + 0) * HH + j], Wh[(size_t)(kb + 1) * HH + j],
                                Wh[(size_t)(kb + 2) * HH + j], Wh[(size_t)(kb + 3) * HH + j]);
        sWi1[idx] = make_float4(Wi1g[(size_t)(kb + 0) * HH + j], Wi1g[(size_t)(kb + 1) * HH + j],
                                Wi1g[(size_t)(kb + 2) * HH + j], Wi1g[(size_t)(kb + 3) * HH + j]);
        sWh1[idx] = make_float4(Wh1g[(size_t)(kb + 0) * HH + j], Wh1g[(size_t)(kb + 1) * HH + j],
                                Wh1g[(size_t)(kb + 2) * HH + j], Wh1g[(size_t)(kb + 3) * HH + j]);
    }

    float bs1[2], b0r[2];
#pragma unroll
    for (int e = 0; e < 2; ++e) {
        bs1[e] = __ldg(&bi[HH + j0 + c0 + e]) + __ldg(&bh[HH + j0 + c0 + e]);
        b0r[e] = __ldg(&bh[j0 + c0 + e]);
    }

    /* h1 init: CTA covers k4 in [2*cta, 2*cta+2), broadcast h0 layer 1. */
    for (int idx = th; idx < 2 * BB; idx += NTH) {
        int k4l = idx >> 7, b = idx & 127;
        g_h1buf[1][(2 * cta + k4l) * BB + b] = *(const float4*)(h0 + HH + 4 * (2 * cta + k4l));
    }
    __syncthreads();

    /* hn0[0] init: dot0[col] = h0_l0 @ Wh0 (shared over batch rows). */
    {
        u64 d[NJ];
#pragma unroll
        for (int jj = 0; jj < NJ; ++jj) d[jj] = 0ull;
        for (int kk = 0; kk < K4G; ++kk) {
            int off = g * K4G + kk;
            ulonglong2 a = *(const ulonglong2*)(h0 + 4 * off);
#pragma unroll
            for (int jj = 0; jj < NJ; ++jj) {
                ulonglong2 w = *(const ulonglong2*)&sWh0[jj * 256 + off];
                d[jj] = fma2(a.x, w.x, fma2(a.y, w.y, d[jj]));
            }
        }
        if (slot == 0) {
#pragma unroll
            for (int jj = 0; jj < NJ; ++jj) {
                float2 f = unpk(d[jj]);
                sdot[g * 8 + jj] = f.x + f.y;
            }
        }
        __syncthreads();
        const float* preF = (const float*)g_pre0;
        const float* h0bW = (float*)g_h0buf[0];
#pragma unroll
        for (int e = 0; e < 2; ++e) {
            int col = c0 + e;
            float dv = 0.0f;
#pragma unroll
            for (int g2 = 0; g2 < 8; ++g2) dv += sdot[g2 * 8 + col];
            int jg4 = (j0 + col) >> 2;
            float pre = preF[((size_t)(0 * KG + jg4) * BB + frow) * 4 + (col & 3)];
            ((float*)h0bW)[((size_t)jg4 * BB + frow) * 4 + (col & 3)] = tanhf(pre + dv + b0r[e]);
        }
    }

    unsigned int ph = 1;
    grid_sync(ph * NBLK); ++ph;

    for (int t = 0; t < TT; ++t) {
        const float4* A0 = g_h0buf[t & 1];
        const float4* A1 = g_h1buf[(t + 1) & 1];
        const float4* p0 = A0 + (size_t)g * K4G * BB + slot;
        const float4* p1 = A1 + (size_t)g * K4G * BB + slot;

        u64 acc1r0[NJ], acc1r1[NJ], acc0r0[NJ], acc0r1[NJ];
#pragma unroll
        for (int jj = 0; jj < NJ; ++jj) {
            acc1r0[jj] = 0ull; acc1r1[jj] = 0ull;
            acc0r0[jj] = 0ull; acc0r1[jj] = 0ull;
        }

        /* Loop 1: A0 feeds Wi1 (acc1) and Wh0 (acc0). */
        {
            u64 nax, nay, nbx, nby;
            ldcg2(p0, nax, nay); ldcg2(p0 + 64, nbx, nby);
#pragma unroll 2
            for (int kk = 0; kk < K4G; ++kk) {
                u64 cax = nax, cay = nay, cbx = nbx, cby = nby;
                if (kk + 1 < K4G) {
                    ldcg2(p0 + (kk + 1) * BB, nax, nay);
                    ldcg2(p0 + (kk + 1) * BB + 64, nbx, nby);
                }
                int off = g * K4G + kk;
#pragma unroll
                for (int jj = 0; jj < NJ; ++jj) {
                    ulonglong2 w1 = *(const ulonglong2*)&sWi1[jj * 256 + off];
                    acc1r0[jj] = fma2(cax, w1.x, fma2(cay, w1.y, acc1r0[jj]));
                    acc1r1[jj] = fma2(cbx, w1.x, fma2(cby, w1.y, acc1r1[jj]));
                    ulonglong2 w0 = *(const ulonglong2*)&sWh0[jj * 256 + off];
                    acc0r0[jj] = fma2(cax, w0.x, fma2(cay, w0.y, acc0r0[jj]));
                    acc0r1[jj] = fma2(cbx, w0.x, fma2(cby, w0.y, acc0r1[jj]));
                }
            }
        }
        /* Loop 2: A1 feeds Wh1 (acc1). */
        {
            u64 nax, nay, nbx, nby;
            ldcg2(p1, nax, nay); ldcg2(p1 + 64, nbx, nby);
#pragma unroll 2
            for (int kk = 0; kk < K4G; ++kk) {
                u64 cax = nax, cay = nay, cbx = nbx, cby = nby;
                if (kk + 1 < K4G) {
                    ldcg2(p1 + (kk + 1) * BB, nax, nay);
                    ldcg2(p1 + (kk + 1) * BB + 64, nbx, nby);
                }
                int off = g * K4G + kk;
#pragma unroll
                for (int jj = 0; jj < NJ; ++jj) {
                    ulonglong2 w = *(const ulonglong2*)&sWh1[jj * 256 + off];
                    acc1r0[jj] = fma2(cax, w.x, fma2(cay, w.y, acc1r0[jj]));
                    acc1r1[jj] = fma2(cbx, w.x, fma2(cby, w.y, acc1r1[jj]));
                }
            }
        }

        /* Collapse (lo+hi) and write partials for 8-way K reduction. */
#pragma unroll
        for (int jj = 0; jj < NJ; ++jj) {
            float2 v;
            v = unpk(acc1r0[jj]); sred[RIDX(jj,      g, slot)] = v.x + v.y;
            v = unpk(acc1r1[jj]); sred[RIDX(jj + 8,  g, slot)] = v.x + v.y;
            v = unpk(acc0r0[jj]); sred[RIDX(jj + 16, g, slot)] = v.x + v.y;
            v = unpk(acc0r1[jj]); sred[RIDX(jj + 24, g, slot)] = v.x + v.y;
        }
        __syncthreads();

        /* Final pass: all 512 threads, 2 (row,col) scalars each. */
        {
            float* h1w = (float*)g_h1buf[t & 1];
#pragma unroll
            for (int e = 0; e < 2; ++e) {
                int col = c0 + e;
                float s1 = 0.0f;
#pragma unroll
                for (int g2 = 0; g2 < 8; ++g2) s1 += sred[RIDX(col + 8 * frh, g2, fslot)];
                float y = tanhf(s1 + bs1[e]);
                int jg4 = (j0 + col) >> 2;
                out[((size_t)frow * TT + t) * HH + j0 + col] = y;
                h1w[((size_t)jg4 * BB + frow) * 4 + (col & 3)] = y;

                if (t < TT - 1) {
                    float s0 = 0.0f;
#pragma unroll
                    for (int g2 = 0; g2 < 8; ++g2) s0 += sred[RIDX(col + 8 * (2 + frh), g2, fslot)];
                    float pre = ((const float*)g_pre0)[((size_t)((size_t)(t + 1) * KG + jg4) * BB + frow) * 4 + (col & 3)];
                    ((float*)g_h0buf[(t + 1) & 1])[((size_t)jg4 * BB + frow) * 4 + (col & 3)] =
                        tanhf(s0 + pre + b0r[e]);
                } else {
                    float* hn = out + (size_t)BB * TT * HH;
                    hn[(size_t)(frow * 2 + 1) * HH + j0 + col] = y;
                    float l0 = __ldcg(&((const float*)g_h0buf[t & 1])[((size_t)jg4 * BB + frow) * 4 + (col & 3)]);
                    hn[(size_t)(frow * 2) * HH + j0 + col] = l0;
                }
            }
        }

        if (t < TT - 1) { grid_sync(ph * NBLK); ++ph; }
    }
}

/* ------------------------------------------------------------------ */
extern "C" void kernel_launch(void* const* d_in, const int* in_sizes, int n_in,
                              void* d_out, int out_size)
{
    const float* x  = (const float*)d_in[0];
    const float* h0 = (const float*)d_in[1];
    const float* Wi = (const float*)d_in[2];
    const float* bi = (const float*)d_in[3];
    const float* Wh = (const float*)d_in[4];
    const float* bh = (const float*)d_in[5];
    float* out = (float*)d_out;

    dim3 g2(16, 256);
    pre_gemm<<<g2, 256>>>(x, Wi, bi);

    size_t smem = 6144 * sizeof(float4) + (32 * 8 * 65 + 64) * sizeof(float);  /* ~161.5 KB */
    cudaFuncSetAttribute(rnn_persist, cudaFuncAttributeMaxDynamicSharedMemorySize, (int)smem);
    rnn_persist<<<NBLK, NTH, smem>>>(h0, Wi, bi, Wh, bh, out);
}